// round 15
// baseline (speedup 1.0000x reference)
#include <cuda_runtime.h>
#include <math.h>

#define FULL 0xffffffffu
#define NMAT 38400
#define WPB 4
#define SHIFT 4.0f

typedef unsigned long long u64;

// 38400 * 576 = 22118400 floats (88.5 MB) each — allowed __device__ scratch
__device__ float g_s1[22118400];
__device__ float g_s2[22118400];

// ---------------- packed f32x2 helpers (Blackwell sm_103a) -----------------
__device__ __forceinline__ u64 pk2(float a, float b) {
  u64 r; asm("mov.b64 %0, {%1, %2};" : "=l"(r) : "f"(a), "f"(b)); return r;
}
__device__ __forceinline__ void upk2(u64 v, float &a, float &b) {
  asm("mov.b64 {%0, %1}, %2;" : "=f"(a), "=f"(b) : "l"(v));
}
__device__ __forceinline__ u64 fma2(u64 a, u64 b, u64 c) {
  u64 d; asm("fma.rn.f32x2 %0, %1, %2, %3;" : "=l"(d) : "l"(a), "l"(b), "l"(c));
  return d;
}
__device__ __forceinline__ u64 mul2(u64 a, u64 b) {
  u64 d; asm("mul.rn.f32x2 %0, %1, %2;" : "=l"(d) : "l"(a), "l"(b)); return d;
}
__device__ __forceinline__ u64 add2(u64 a, u64 b) {
  u64 d; asm("add.rn.f32x2 %0, %1, %2;" : "=l"(d) : "l"(a), "l"(b)); return d;
}
__device__ __forceinline__ float hsum2(u64 v) {
  float a, b; upk2(v, a, b); return a + b;
}

// ---------------------------------------------------------------------------
// Warp-parallel Cholesky of SPD 24x24, packed: lane j holds column j as 12
// f32x2 words (elements 2t, 2t+1). Right-looking; multiplier l[j,k] is a
// compile-time-indexed element of the lane's OWN column. The j-loop starts at
// k/2 — elements below that land in the i<lane junk region zeroed at the end.
// Idle lanes (>=24) carry zeros and stay zero.
// ---------------------------------------------------------------------------
__device__ __forceinline__ void chol24_2(u64 (&x)[12], int lane) {
#pragma unroll
  for (int k = 0; k < 24; k++) {
    u64 pv = __shfl_sync(FULL, x[k >> 1], k);      // pivot word
    float p0, p1; upk2(pv, p0, p1);
    float dk = (k & 1) ? p1 : p0;
    float rd = rsqrtf(dk);
    float q0, q1; upk2(x[k >> 1], q0, q1);
    float ljk = ((k & 1) ? q1 : q0) * rd;          // own element k
    float sel = (lane > k) ? -ljk : 0.f;
    u64 sel2 = pk2(sel, sel);
    u64 rd2  = pk2(rd, rd);
    bool isk = (lane == k);
#pragma unroll
    for (int j = k >> 1; j < 12; j++) {
      u64 lki = mul2(__shfl_sync(FULL, x[j], k), rd2);
      u64 upd = fma2(sel2, lki, x[j]);
      x[j] = isk ? lki : upd;
    }
  }
  // zero elements i < lane of own column (strict upper + update junk)
#pragma unroll
  for (int j = 0; j < 12; j++) {
    float z0, z1; upk2(x[j], z0, z1);
    if (2 * j     < lane) z0 = 0.f;
    if (2 * j + 1 < lane) z1 = 0.f;
    x[j] = pk2(z0, z1);
  }
}

// ---------------------------------------------------------------------------
// One-sided Jacobi column orthogonalization of a 24x24 factor, packed.
// Lane j = column j as 12 f32x2 words. Implicit Gram = M^T M; sigma^2 =
// ||col||^2; spectral f of M M^T = recompose(cols, f(ss)/ss). Valid only on
// explicit factors (R8 lesson: on a symmetric matrix it squares cond).
// apq identical on both pair lanes: elementwise products commute, packed
// accumulation order identical. c,s scalar per lane, broadcast into f32x2.
// ---------------------------------------------------------------------------
template <int NS>
__device__ __forceinline__ void jacobi1s2(u64 (&b)[12], int lane) {
  float app;
  {
    u64 a0 = 0ULL, a1 = 0ULL;
#pragma unroll
    for (int j = 0; j < 12; j += 2) {
      a0 = fma2(b[j], b[j], a0);
      a1 = fma2(b[j + 1], b[j + 1], a1);
    }
    app = hsum2(add2(a0, a1));
  }

  for (int sweep = 0; sweep < NS; sweep++) {
#pragma unroll
    for (int r = 0; r < 23; r++) {
      int partner;
      if (lane >= 24)      partner = lane;
      else if (lane == 23) partner = r;
      else if (lane == r)  partner = 23;
      else                 partner = (2 * r + 23 - lane) % 23;

      u64 bp[12];
      u64 d0 = 0ULL, d1 = 0ULL;
#pragma unroll
      for (int j = 0; j < 12; j += 2) {
        bp[j] = __shfl_sync(FULL, b[j], partner);
        d0 = fma2(b[j], bp[j], d0);
        bp[j + 1] = __shfl_sync(FULL, b[j + 1], partner);
        d1 = fma2(b[j + 1], bp[j + 1], d1);
      }
      float apq = hsum2(add2(d0, d1));     // identical on both pair lanes
      float nq  = __shfl_sync(FULL, app, partner);
      bool  isLow = lane <= partner;
      float nlow  = isLow ? app : nq;
      float nhigh = isLow ? nq : app;

      float c, s, tt;
      if (fabsf(apq) > 1e-30f) {
        float tau = (nhigh - nlow) / (2.0f * apq);
        tt = ((tau >= 0.f) ? 1.f : -1.f) /
             (fabsf(tau) + sqrtf(fmaf(tau, tau, 1.f)));
        c = rsqrtf(fmaf(tt, tt, 1.f));
        s = tt * c;
      } else { c = 1.f; s = 0.f; tt = 0.f; }

      float tse = isLow ? -tt : tt;
      app = fmaf(tse, apq, app);           // norm^2 update (exact Jacobi law)
      float se = isLow ? -s : s;
      u64 c2  = pk2(c, c);
      u64 se2 = pk2(se, se);
#pragma unroll
      for (int j = 0; j < 12; j++)
        b[j] = fma2(se2, bp[j], mul2(c2, b[j]));   // packed column rotation
    }
  }
}

// ---------------------------------------------------------------------------
// R = sum_k f_k col_k col_k^T, packed. u = columns (12 f32x2 per lane),
// f per-lane scalar. tb = per-warp smem scratch (>= 600 floats).
// Transposed factor is RE-READ from smem inside the k-loop (one conflict-free
// LDS per k) instead of a ut[24] register array — keeps live regs low so the
// kernel fits 102 regs (5 blocks/SM on the 64K-reg file).
// ---------------------------------------------------------------------------
__device__ __forceinline__ void recompose24_2(const u64 (&u)[12], float f,
                                              u64 (&r)[12], int lane,
                                              float *tb) {
  __syncwarp();
  if (lane < 24) {
#pragma unroll
    for (int j = 0; j < 12; j++) {
      float a, b; upk2(u[j], a, b);
      tb[lane * 25 + 2 * j]     = a;
      tb[lane * 25 + 2 * j + 1] = b;
    }
  }
  __syncwarp();
  int ln = (lane < 24) ? lane : 0;

  u64 f2 = pk2(f, f);
  u64 m[12];
#pragma unroll
  for (int j = 0; j < 12; j++) { m[j] = mul2(u[j], f2); r[j] = 0ULL; }
#pragma unroll
  for (int k = 0; k < 24; k++) {
    float coef = tb[k * 25 + ln];          // U[lane][k]
    u64 c2 = pk2(coef, coef);
#pragma unroll
    for (int j = 0; j < 12; j++)
      r[j] = fma2(__shfl_sync(FULL, m[j], k), c2, r[j]);
  }
  __syncwarp();
}

// packed ||col||^2
__device__ __forceinline__ float colnorm2(const u64 (&b)[12]) {
  u64 a0 = 0ULL, a1 = 0ULL;
#pragma unroll
  for (int j = 0; j < 12; j += 2) {
    a0 = fma2(b[j], b[j], a0);
    a1 = fma2(b[j + 1], b[j + 1], a1);
  }
  return hsum2(add2(a0, a1));
}

// ---------------------------------------------------------------------------
// K1: x -> sym_logm(x) via Cholesky + packed one-sided Jacobi. 5 sweeps.
// ---------------------------------------------------------------------------
__global__ void __launch_bounds__(128, 5) k_logm(const float *__restrict__ x) {
  __shared__ float tbuf[WPB][600];
  int wid = threadIdx.x >> 5, lane = threadIdx.x & 31;
  int m = blockIdx.x * WPB + wid;
  const float *src = x + (size_t)m * 576;

  u64 a[12];
#pragma unroll
  for (int j = 0; j < 12; j++) {
    float e0 = (lane < 24) ? src[(2 * j) * 24 + lane] : 0.f;
    float e1 = (lane < 24) ? src[(2 * j + 1) * 24 + lane] : 0.f;
    a[j] = pk2(e0, e1);
  }

  chol24_2(a, lane);
  jacobi1s2<5>(a, lane);

  float ss = fmaxf(colnorm2(a), 1e-24f);
  float f = logf(ss) / ss;               // log(lambda)/lambda, lambda = ss

  u64 r[12];
  recompose24_2(a, f, r, lane, tbuf[wid]);

  float *dst = g_s1 + (size_t)m * 576;
  if (lane < 24) {
#pragma unroll
    for (int j = 0; j < 12; j++) {
      float e0, e1; upk2(r[j], e0, e1);
      dst[(2 * j) * 24 + lane]     = e0;
      dst[(2 * j + 1) * 24 + lane] = e1;
    }
  }
}

// ---------------------------------------------------------------------------
// K2: tangent-space aggregation (unchanged).
// ---------------------------------------------------------------------------
__global__ void __launch_bounds__(800) k_agg(const float *__restrict__ A) {
  __shared__ float As[625];
  int g = blockIdx.x;
  for (int e = threadIdx.x; e < 625; e += 800) As[e] = A[(size_t)g * 625 + e];
  __syncthreads();

  int j = threadIdx.x >> 5;
  int lane = threadIdx.x & 31;
  float av[25];
#pragma unroll
  for (int vv = 0; vv < 25; vv++) av[vv] = As[vv * 25 + j];

  const float *src = g_s1 + (size_t)g * 14400;
  float *dst = g_s2 + ((size_t)g * 25 + j) * 576;
  for (int it = 0; it < 18; it++) {
    int idx = lane + it * 32;
    float acc = 0.f;
#pragma unroll
    for (int vv = 0; vv < 25; vv++)
      acc = fmaf(av[vv], __ldg(src + vv * 576 + idx), acc);
    dst[idx] = acc;
  }
}

// ---------------------------------------------------------------------------
// K3: factor-based epilogue (packed):
//   stage A: L+SHIFT*I = C C^T (cond<2 -> 4 sweeps); lambda = ss - SHIFT;
//            M col = (W col) * e^{lambda/2}/sigma (scalar matmul, W in smem).
//   stage B: Z = M M^T (never formed); packed one-sided (6 sweeps) ->
//            sigma'^2 = eig(Z); ||Z||_F = sqrt(sum sigma'^4);
//            out = sqrt(Z/||Z||) = recompose(M', rsqrt(ss' * c)).
// ---------------------------------------------------------------------------
__global__ void __launch_bounds__(128, 5) k_final(const float *__restrict__ Wm,
                                                  float *__restrict__ out) {
  __shared__ float tbuf[WPB][600];
  __shared__ float Ws[576];
  for (int t = threadIdx.x; t < 576; t += 128) Ws[t] = Wm[t];
  __syncthreads();

  int wid = threadIdx.x >> 5, lane = threadIdx.x & 31;
  int mIdx = blockIdx.x * WPB + wid;

  const float *src = g_s2 + (size_t)mIdx * 576;
  u64 a[12];
#pragma unroll
  for (int j = 0; j < 12; j++) {
    float e0 = (lane < 24) ? src[(2 * j) * 24 + lane] : 0.f;
    float e1 = (lane < 24) ? src[(2 * j + 1) * 24 + lane] : 0.f;
    if (2 * j == lane)     e0 += SHIFT;    // diagonal shift
    if (2 * j + 1 == lane) e1 += SHIFT;
    a[j] = pk2(e0, e1);
  }

  // stage A: shifted Cholesky + one-sided Jacobi (cond<2 -> 4 sweeps)
  chol24_2(a, lane);
  jacobi1s2<4>(a, lane);

  float ss = colnorm2(a);
  float ssg = fmaxf(ss, 1e-24f);
  float lam = ss - SHIFT;                      // eigenvalue of L
  float scl = expf(0.5f * lam) * rsqrtf(ssg);  // e^{lam/2} / sigma

  // M column j = (W * col_j) * scl ; W broadcast from smem, no shuffles.
  float v[24];
#pragma unroll
  for (int j = 0; j < 12; j++) upk2(a[j], v[2 * j], v[2 * j + 1]);

  u64 mm[12];
  u64 scl2 = pk2(scl, scl);
#pragma unroll
  for (int j = 0; j < 12; j++) {
    float acc0 = 0.f, acc1 = 0.f;
    const float4 *w0 = (const float4 *)&Ws[(2 * j) * 24];
    const float4 *w1 = (const float4 *)&Ws[(2 * j + 1) * 24];
#pragma unroll
    for (int k4 = 0; k4 < 6; k4++) {
      float4 wa = w0[k4], wb = w1[k4];
      acc0 = fmaf(wa.x, v[k4 * 4 + 0], acc0);
      acc0 = fmaf(wa.y, v[k4 * 4 + 1], acc0);
      acc0 = fmaf(wa.z, v[k4 * 4 + 2], acc0);
      acc0 = fmaf(wa.w, v[k4 * 4 + 3], acc0);
      acc1 = fmaf(wb.x, v[k4 * 4 + 0], acc1);
      acc1 = fmaf(wb.y, v[k4 * 4 + 1], acc1);
      acc1 = fmaf(wb.z, v[k4 * 4 + 2], acc1);
      acc1 = fmaf(wb.w, v[k4 * 4 + 3], acc1);
    }
    mm[j] = mul2(pk2(acc0, acc1), scl2);
  }

  // stage B: one-sided Jacobi on M (accuracy-critical: keep 6 sweeps)
  jacobi1s2<6>(mm, lane);

  float ss2 = colnorm2(mm);

  // c = ||Z||_F = sqrt(sum sigma^4); idle lanes contribute 0
  float s4 = ss2 * ss2;
#pragma unroll
  for (int off = 16; off > 0; off >>= 1) s4 += __shfl_xor_sync(FULL, s4, off);
  float c = sqrtf(fmaxf(s4, 1e-30f));

  // per-column scalar: (sigma/sqrt(c))/sigma^2 = 1/(sigma*sqrt(c))
  float fscl = rsqrtf(fmaxf(ss2, 1e-24f) * c);

  u64 r[12];
  recompose24_2(mm, fscl, r, lane, tbuf[wid]);

  float *dst = out + (size_t)mIdx * 576;
  if (lane < 24) {
#pragma unroll
    for (int j = 0; j < 12; j++) {
      float e0, e1; upk2(r[j], e0, e1);
      dst[(2 * j) * 24 + lane]     = e0;
      dst[(2 * j + 1) * 24 + lane] = e1;
    }
  }
}

// ---------------------------------------------------------------------------
extern "C" void kernel_launch(void *const *d_in, const int *in_sizes, int n_in,
                              void *d_out, int out_size) {
  const float *x = nullptr, *A = nullptr, *Wm = nullptr;
  for (int i = 0; i < n_in; i++) {
    if (in_sizes[i] == 22118400)     x  = (const float *)d_in[i];
    else if (in_sizes[i] == 960000)  A  = (const float *)d_in[i];
    else if (in_sizes[i] == 576)     Wm = (const float *)d_in[i];
  }
  float *out = (float *)d_out;

  k_logm<<<NMAT / WPB, 128>>>(x);
  k_agg<<<1536, 800>>>(A);
  k_final<<<NMAT / WPB, 128>>>(Wm, out);
}

// round 17
// speedup vs baseline: 1.0310x; 1.0310x over previous
#include <cuda_runtime.h>
#include <math.h>

#define FULL 0xffffffffu
#define NMAT 38400
#define WPB 4
#define SHIFT 4.0f

typedef unsigned long long u64;

// 38400 * 576 = 22118400 floats (88.5 MB) each — allowed __device__ scratch
__device__ float g_s1[22118400];
__device__ float g_s2[22118400];

// ---------------- packed f32x2 helpers (Blackwell sm_103a) -----------------
__device__ __forceinline__ u64 pk2(float a, float b) {
  u64 r; asm("mov.b64 %0, {%1, %2};" : "=l"(r) : "f"(a), "f"(b)); return r;
}
__device__ __forceinline__ void upk2(u64 v, float &a, float &b) {
  asm("mov.b64 {%0, %1}, %2;" : "=f"(a), "=f"(b) : "l"(v));
}
__device__ __forceinline__ u64 fma2(u64 a, u64 b, u64 c) {
  u64 d; asm("fma.rn.f32x2 %0, %1, %2, %3;" : "=l"(d) : "l"(a), "l"(b), "l"(c));
  return d;
}
__device__ __forceinline__ u64 mul2(u64 a, u64 b) {
  u64 d; asm("mul.rn.f32x2 %0, %1, %2;" : "=l"(d) : "l"(a), "l"(b)); return d;
}
__device__ __forceinline__ u64 add2(u64 a, u64 b) {
  u64 d; asm("add.rn.f32x2 %0, %1, %2;" : "=l"(d) : "l"(a), "l"(b)); return d;
}
__device__ __forceinline__ float hsum2(u64 v) {
  float a, b; upk2(v, a, b); return a + b;
}

// ---------------------------------------------------------------------------
// Warp-parallel Cholesky of SPD 24x24, packed: lane j holds column j as 12
// f32x2 words. Right-looking; multiplier l[j,k] is a compile-time-indexed
// element of the lane's OWN column. j-loop starts at k/2 (junk zeroed below).
// ---------------------------------------------------------------------------
__device__ __forceinline__ void chol24_2(u64 (&x)[12], int lane) {
#pragma unroll
  for (int k = 0; k < 24; k++) {
    u64 pv = __shfl_sync(FULL, x[k >> 1], k);      // pivot word
    float p0, p1; upk2(pv, p0, p1);
    float dk = (k & 1) ? p1 : p0;
    float rd = rsqrtf(dk);
    float q0, q1; upk2(x[k >> 1], q0, q1);
    float ljk = ((k & 1) ? q1 : q0) * rd;          // own element k
    float sel = (lane > k) ? -ljk : 0.f;
    u64 sel2 = pk2(sel, sel);
    u64 rd2  = pk2(rd, rd);
    bool isk = (lane == k);
#pragma unroll
    for (int j = k >> 1; j < 12; j++) {
      u64 lki = mul2(__shfl_sync(FULL, x[j], k), rd2);
      u64 upd = fma2(sel2, lki, x[j]);
      x[j] = isk ? lki : upd;
    }
  }
#pragma unroll
  for (int j = 0; j < 12; j++) {
    float z0, z1; upk2(x[j], z0, z1);
    if (2 * j     < lane) z0 = 0.f;
    if (2 * j + 1 < lane) z1 = 0.f;
    x[j] = pk2(z0, z1);
  }
}

// ---------------------------------------------------------------------------
// One-sided Jacobi column orthogonalization of a 24x24 factor, packed.
// Valid only on explicit factors (R8: on a symmetric matrix it squares cond).
// Sweep frontier (calibrated R12-R15): K1=5, stageA=4, stageB=6 — all tight.
// ---------------------------------------------------------------------------
template <int NS>
__device__ __forceinline__ void jacobi1s2(u64 (&b)[12], int lane) {
  float app;
  {
    u64 a0 = 0ULL, a1 = 0ULL;
#pragma unroll
    for (int j = 0; j < 12; j += 2) {
      a0 = fma2(b[j], b[j], a0);
      a1 = fma2(b[j + 1], b[j + 1], a1);
    }
    app = hsum2(add2(a0, a1));
  }

  for (int sweep = 0; sweep < NS; sweep++) {
#pragma unroll
    for (int r = 0; r < 23; r++) {
      int partner;
      if (lane >= 24)      partner = lane;
      else if (lane == 23) partner = r;
      else if (lane == r)  partner = 23;
      else                 partner = (2 * r + 23 - lane) % 23;

      u64 bp[12];
      u64 d0 = 0ULL, d1 = 0ULL;
#pragma unroll
      for (int j = 0; j < 12; j += 2) {
        bp[j] = __shfl_sync(FULL, b[j], partner);
        d0 = fma2(b[j], bp[j], d0);
        bp[j + 1] = __shfl_sync(FULL, b[j + 1], partner);
        d1 = fma2(b[j + 1], bp[j + 1], d1);
      }
      float apq = hsum2(add2(d0, d1));     // identical on both pair lanes
      float nq  = __shfl_sync(FULL, app, partner);
      bool  isLow = lane <= partner;
      float nlow  = isLow ? app : nq;
      float nhigh = isLow ? nq : app;

      float c, s, tt;
      if (fabsf(apq) > 1e-30f) {
        float tau = (nhigh - nlow) / (2.0f * apq);
        tt = ((tau >= 0.f) ? 1.f : -1.f) /
             (fabsf(tau) + sqrtf(fmaf(tau, tau, 1.f)));
        c = rsqrtf(fmaf(tt, tt, 1.f));
        s = tt * c;
      } else { c = 1.f; s = 0.f; tt = 0.f; }

      float tse = isLow ? -tt : tt;
      app = fmaf(tse, apq, app);           // norm^2 update (exact Jacobi law)
      float se = isLow ? -s : s;
      u64 c2  = pk2(c, c);
      u64 se2 = pk2(se, se);
#pragma unroll
      for (int j = 0; j < 12; j++)
        b[j] = fma2(se2, bp[j], mul2(c2, b[j]));   // packed column rotation
    }
  }
}

// ---------------------------------------------------------------------------
// recompose, SMEM-coef variant (low registers — used by k_logm @ 5 blocks/SM)
// ---------------------------------------------------------------------------
__device__ __forceinline__ void recompose24_2s(const u64 (&u)[12], float f,
                                               u64 (&r)[12], int lane,
                                               float *tb) {
  __syncwarp();
  if (lane < 24) {
#pragma unroll
    for (int j = 0; j < 12; j++) {
      float a, b; upk2(u[j], a, b);
      tb[lane * 25 + 2 * j]     = a;
      tb[lane * 25 + 2 * j + 1] = b;
    }
  }
  __syncwarp();
  int ln = (lane < 24) ? lane : 0;

  u64 f2 = pk2(f, f);
  u64 m[12];
#pragma unroll
  for (int j = 0; j < 12; j++) { m[j] = mul2(u[j], f2); r[j] = 0ULL; }
#pragma unroll
  for (int k = 0; k < 24; k++) {
    float coef = tb[k * 25 + ln];          // U[lane][k]
    u64 c2 = pk2(coef, coef);
#pragma unroll
    for (int j = 0; j < 12; j++)
      r[j] = fma2(__shfl_sync(FULL, m[j], k), c2, r[j]);
  }
  __syncwarp();
}

// ---------------------------------------------------------------------------
// recompose, register-coef variant (R13 — fastest measured for k_final)
// ---------------------------------------------------------------------------
__device__ __forceinline__ void recompose24_2r(const u64 (&u)[12], float f,
                                               u64 (&r)[12], int lane,
                                               float *tb) {
  __syncwarp();
  if (lane < 24) {
#pragma unroll
    for (int j = 0; j < 12; j++) {
      float a, b; upk2(u[j], a, b);
      tb[lane * 25 + 2 * j]     = a;
      tb[lane * 25 + 2 * j + 1] = b;
    }
  }
  __syncwarp();
  float ut[24];
  int ln = (lane < 24) ? lane : 0;
#pragma unroll
  for (int i = 0; i < 24; i++) ut[i] = tb[i * 25 + ln];

  u64 f2 = pk2(f, f);
  u64 m[12];
#pragma unroll
  for (int j = 0; j < 12; j++) { m[j] = mul2(u[j], f2); r[j] = 0ULL; }
#pragma unroll
  for (int k = 0; k < 24; k++) {
    u64 c2 = pk2(ut[k], ut[k]);
#pragma unroll
    for (int j = 0; j < 12; j++)
      r[j] = fma2(__shfl_sync(FULL, m[j], k), c2, r[j]);
  }
  __syncwarp();
}

// packed ||col||^2
__device__ __forceinline__ float colnorm2(const u64 (&b)[12]) {
  u64 a0 = 0ULL, a1 = 0ULL;
#pragma unroll
  for (int j = 0; j < 12; j += 2) {
    a0 = fma2(b[j], b[j], a0);
    a1 = fma2(b[j + 1], b[j + 1], a1);
  }
  return hsum2(add2(a0, a1));
}

// ---------------------------------------------------------------------------
// K1: x -> sym_logm(x). Cholesky + one-sided Jacobi, 5 sweeps.
// R14 config: (128,5) bounds + smem-coef recompose (measured 939.5 us).
// ---------------------------------------------------------------------------
__global__ void __launch_bounds__(128, 5) k_logm(const float *__restrict__ x) {
  __shared__ float tbuf[WPB][600];
  int wid = threadIdx.x >> 5, lane = threadIdx.x & 31;
  int m = blockIdx.x * WPB + wid;
  const float *src = x + (size_t)m * 576;

  u64 a[12];
#pragma unroll
  for (int j = 0; j < 12; j++) {
    float e0 = (lane < 24) ? src[(2 * j) * 24 + lane] : 0.f;
    float e1 = (lane < 24) ? src[(2 * j + 1) * 24 + lane] : 0.f;
    a[j] = pk2(e0, e1);
  }

  chol24_2(a, lane);
  jacobi1s2<5>(a, lane);

  float ss = fmaxf(colnorm2(a), 1e-24f);
  float f = logf(ss) / ss;               // log(lambda)/lambda, lambda = ss

  u64 r[12];
  recompose24_2s(a, f, r, lane, tbuf[wid]);

  float *dst = g_s1 + (size_t)m * 576;
  if (lane < 24) {
#pragma unroll
    for (int j = 0; j < 12; j++) {
      float e0, e1; upk2(r[j], e0, e1);
      dst[(2 * j) * 24 + lane]     = e0;
      dst[(2 * j + 1) * 24 + lane] = e1;
    }
  }
}

// ---------------------------------------------------------------------------
// K2: tangent-space aggregation (unchanged).
// ---------------------------------------------------------------------------
__global__ void __launch_bounds__(800) k_agg(const float *__restrict__ A) {
  __shared__ float As[625];
  int g = blockIdx.x;
  for (int e = threadIdx.x; e < 625; e += 800) As[e] = A[(size_t)g * 625 + e];
  __syncthreads();

  int j = threadIdx.x >> 5;
  int lane = threadIdx.x & 31;
  float av[25];
#pragma unroll
  for (int vv = 0; vv < 25; vv++) av[vv] = As[vv * 25 + j];

  const float *src = g_s1 + (size_t)g * 14400;
  float *dst = g_s2 + ((size_t)g * 25 + j) * 576;
  for (int it = 0; it < 18; it++) {
    int idx = lane + it * 32;
    float acc = 0.f;
#pragma unroll
    for (int vv = 0; vv < 25; vv++)
      acc = fmaf(av[vv], __ldg(src + vv * 576 + idx), acc);
    dst[idx] = acc;
  }
}

// ---------------------------------------------------------------------------
// K3: factor-based epilogue. R13 config (no reg cap, register-coef
// recompose). Stage A = 4 sweeps (R15 proved 3 fails: eigvector error from
// an under-converged Gram feeds M and passes through stage B at full weight).
// ---------------------------------------------------------------------------
__global__ void __launch_bounds__(128) k_final(const float *__restrict__ Wm,
                                               float *__restrict__ out) {
  __shared__ float tbuf[WPB][600];
  __shared__ float Ws[576];
  for (int t = threadIdx.x; t < 576; t += 128) Ws[t] = Wm[t];
  __syncthreads();

  int wid = threadIdx.x >> 5, lane = threadIdx.x & 31;
  int mIdx = blockIdx.x * WPB + wid;

  const float *src = g_s2 + (size_t)mIdx * 576;
  u64 a[12];
#pragma unroll
  for (int j = 0; j < 12; j++) {
    float e0 = (lane < 24) ? src[(2 * j) * 24 + lane] : 0.f;
    float e1 = (lane < 24) ? src[(2 * j + 1) * 24 + lane] : 0.f;
    if (2 * j == lane)     e0 += SHIFT;    // diagonal shift
    if (2 * j + 1 == lane) e1 += SHIFT;
    a[j] = pk2(e0, e1);
  }

  // stage A: shifted Cholesky + one-sided Jacobi (4 sweeps — tight)
  chol24_2(a, lane);
  jacobi1s2<4>(a, lane);

  float ss = colnorm2(a);
  float ssg = fmaxf(ss, 1e-24f);
  float lam = ss - SHIFT;                      // eigenvalue of L
  float scl = expf(0.5f * lam) * rsqrtf(ssg);  // e^{lam/2} / sigma

  // M column j = (W * col_j) * scl ; W broadcast from smem, no shuffles.
  float v[24];
#pragma unroll
  for (int j = 0; j < 12; j++) upk2(a[j], v[2 * j], v[2 * j + 1]);

  u64 mm[12];
  u64 scl2 = pk2(scl, scl);
#pragma unroll
  for (int j = 0; j < 12; j++) {
    float acc0 = 0.f, acc1 = 0.f;
    const float4 *w0 = (const float4 *)&Ws[(2 * j) * 24];
    const float4 *w1 = (const float4 *)&Ws[(2 * j + 1) * 24];
#pragma unroll
    for (int k4 = 0; k4 < 6; k4++) {
      float4 wa = w0[k4], wb = w1[k4];
      acc0 = fmaf(wa.x, v[k4 * 4 + 0], acc0);
      acc0 = fmaf(wa.y, v[k4 * 4 + 1], acc0);
      acc0 = fmaf(wa.z, v[k4 * 4 + 2], acc0);
      acc0 = fmaf(wa.w, v[k4 * 4 + 3], acc0);
      acc1 = fmaf(wb.x, v[k4 * 4 + 0], acc1);
      acc1 = fmaf(wb.y, v[k4 * 4 + 1], acc1);
      acc1 = fmaf(wb.z, v[k4 * 4 + 2], acc1);
      acc1 = fmaf(wb.w, v[k4 * 4 + 3], acc1);
    }
    mm[j] = mul2(pk2(acc0, acc1), scl2);
  }

  // stage B: one-sided Jacobi on M (accuracy-critical: keep 6 sweeps)
  jacobi1s2<6>(mm, lane);

  float ss2 = colnorm2(mm);

  // c = ||Z||_F = sqrt(sum sigma^4); idle lanes contribute 0
  float s4 = ss2 * ss2;
#pragma unroll
  for (int off = 16; off > 0; off >>= 1) s4 += __shfl_xor_sync(FULL, s4, off);
  float c = sqrtf(fmaxf(s4, 1e-30f));

  // per-column scalar: (sigma/sqrt(c))/sigma^2 = 1/(sigma*sqrt(c))
  float fscl = rsqrtf(fmaxf(ss2, 1e-24f) * c);

  u64 r[12];
  recompose24_2r(mm, fscl, r, lane, tbuf[wid]);

  float *dst = out + (size_t)mIdx * 576;
  if (lane < 24) {
#pragma unroll
    for (int j = 0; j < 12; j++) {
      float e0, e1; upk2(r[j], e0, e1);
      dst[(2 * j) * 24 + lane]     = e0;
      dst[(2 * j + 1) * 24 + lane] = e1;
    }
  }
}

// ---------------------------------------------------------------------------
extern "C" void kernel_launch(void *const *d_in, const int *in_sizes, int n_in,
                              void *d_out, int out_size) {
  const float *x = nullptr, *A = nullptr, *Wm = nullptr;
  for (int i = 0; i < n_in; i++) {
    if (in_sizes[i] == 22118400)     x  = (const float *)d_in[i];
    else if (in_sizes[i] == 960000)  A  = (const float *)d_in[i];
    else if (in_sizes[i] == 576)     Wm = (const float *)d_in[i];
  }
  float *out = (float *)d_out;

  k_logm<<<NMAT / WPB, 128>>>(x);
  k_agg<<<1536, 800>>>(A);
  k_final<<<NMAT / WPB, 128>>>(Wm, out);
}